// round 7
// baseline (speedup 1.0000x reference)
#include <cuda_runtime.h>
#include <math.h>

#define GRID 296          // 2 blocks/SM -> all co-resident (grid barrier safe)
#define CK 8              // k-split for gram
#define SMEM_BYTES 98304  // 96 KB dynamic: 3 stages x 8 warps x 4 KB

// ---------------- scratch (device globals; no allocations) ----------------
__device__ float g_means[2][256][1024];    // per-tensor class sum-of-normalized vectors
__device__ float g_gram[CK][2][256][256];  // partial grams
__device__ float g_rowloss[256];
__device__ int   g_bar1, g_bar2, g_done;   // barrier counters (self-resetting)

__constant__ unsigned char c_ti[10] = {0,0,0,0,1,1,1,2,2,3};
__constant__ unsigned char c_tj[10] = {0,1,2,3,1,2,3,2,3,3};

__device__ __forceinline__ void grid_barrier(int* ctr) {
    __syncthreads();
    if (threadIdx.x == 0) {
        __threadfence();
        atomicAdd(ctr, 1);
        while (*((volatile int*)ctr) < GRID) __nanosleep(64);
    }
    __syncthreads();
}

extern __shared__ __align__(16) unsigned char s_raw[];

__global__ void __launch_bounds__(256, 2)
fused_kernel(const float* __restrict__ emb, const float* __restrict__ feat,
             float* __restrict__ out) {
    __shared__ float s_red[8];
    __shared__ int   s_last;

    int tid = threadIdx.x, lane = tid & 31, w = tid >> 5;

    // ================= phase 1: fused normalize + class mean =================
    // 512 units (tensor x class); block = 8 warps, warp w owns samples
    // [w*8, w*8+8); lane owns float4 chunks j*32+lane of D=1024.
    // 3-stage cp.async staging per warp, wait_group 2 -> 8KB/warp in flight.
    {
        float4* sm4 = (float4*)s_raw;   // [(stage*8 + warp)*256 + pos]

        for (int u = blockIdx.x; u < 512; u += GRID) {
            int c = u & 255, t = u >> 8;
            const float4* base4 = (const float4*)((t == 0 ? emb : feat)
                                   + (size_t)c * 65536) + (size_t)(w * 8) * 256;

            float4 acc[8];
            #pragma unroll
            for (int j = 0; j < 8; j++) acc[j] = make_float4(0.f, 0.f, 0.f, 0.f);

            #define ISSUE(n, st) do {                                                 \
                unsigned _d = (unsigned)__cvta_generic_to_shared(                     \
                                  &sm4[((st) * 8 + w) * 256 + lane]);                 \
                const float4* _s = base4 + (size_t)(n) * 256 + lane;                  \
                _Pragma("unroll")                                                     \
                for (int j = 0; j < 8; j++)                                           \
                    asm volatile("cp.async.cg.shared.global [%0], [%1], 16;"          \
                                 :: "r"(_d + j * 512), "l"(_s + j * 32));             \
                asm volatile("cp.async.commit_group;");                               \
            } while (0)

            ISSUE(0, 0); ISSUE(1, 1); ISSUE(2, 2);

            #pragma unroll 1
            for (int n = 0; n < 8; n++) {
                asm volatile("cp.async.wait_group 2;" ::: "memory");
                int st = n % 3;
                const float4* sb = &sm4[(st * 8 + w) * 256];

                float4 v[8];
                #pragma unroll
                for (int j = 0; j < 8; j++) v[j] = sb[j * 32 + lane];

                // free the stage immediately for the next prefetch
                if (n + 3 < 8) { ISSUE(n + 3, st); }
                else { asm volatile("cp.async.commit_group;"); }

                float ss = 0.f;
                #pragma unroll
                for (int j = 0; j < 8; j++)
                    ss += v[j].x * v[j].x + v[j].y * v[j].y
                        + v[j].z * v[j].z + v[j].w * v[j].w;
                #pragma unroll
                for (int o = 16; o; o >>= 1) ss += __shfl_xor_sync(0xffffffffu, ss, o);
                float inv = 1.0f / fmaxf(sqrtf(ss), 1e-12f);

                #pragma unroll
                for (int j = 0; j < 8; j++) {
                    acc[j].x += v[j].x * inv;
                    acc[j].y += v[j].y * inv;
                    acc[j].z += v[j].z * inv;
                    acc[j].w += v[j].w * inv;
                }
            }
            #undef ISSUE

            // cross-warp combine in stage-0 area (each warp drained its own groups)
            __syncthreads();
            #pragma unroll
            for (int j = 0; j < 8; j++) sm4[w * 256 + j * 32 + lane] = acc[j];
            __syncthreads();
            {
                float4 r = sm4[tid];   // position tid, warp 0 slice base
                #pragma unroll
                for (int w2 = 1; w2 < 8; w2++) {
                    float4 vv = sm4[w2 * 256 + tid];
                    r.x += vv.x; r.y += vv.y; r.z += vv.z; r.w += vv.w;
                }
                ((float4*)&g_means[t][c][0])[tid] = r;  // SUM; /64 folded into gram
            }
            __syncthreads();  // protect staging before next unit's ISSUE
        }
    }

    grid_barrier(&g_bar1);

    // ================= phase 2: gram = means @ means^T =================
    // 160 active blocks: 2 tensors x 10 upper-tri 64x64 tiles x CK=8 k-chunks.
    // 256 threads, 4x4 micro-tile, fma.rn.f32x2 inner loop. Mirror writes.
    if (blockIdx.x < 20 * CK) {
        int b   = blockIdx.x;
        int it  = b >> 3;
        int ks  = b & 7;
        int t   = it >= 10;
        int tri = it - t * 10;
        int i0 = c_ti[tri] * 64, j0 = c_tj[tri] * 64;
        const float* A = &g_means[t][0][0];

        float (*As)[68] = (float(*)[68])s_raw;             // 64x68
        float (*Bs)[68] = (float(*)[68])(s_raw + 17408);

        int tx = tid & 15, ty = tid >> 4;
        unsigned long long acc[4][2];
        #pragma unroll
        for (int uu = 0; uu < 4; uu++) { acc[uu][0] = 0ull; acc[uu][1] = 0ull; }

        int kbase = ks * 128;
        for (int kk = kbase; kk < kbase + 128; kk += 64) {
            #pragma unroll
            for (int l = 0; l < 4; l++) {
                int idx = tid + l * 256;
                int r = idx >> 4, f4 = idx & 15;
                float4 va = *(const float4*)&A[(size_t)(i0 + r) * 1024 + kk + f4 * 4];
                As[f4 * 4 + 0][r] = va.x;
                As[f4 * 4 + 1][r] = va.y;
                As[f4 * 4 + 2][r] = va.z;
                As[f4 * 4 + 3][r] = va.w;
                float4 vb = *(const float4*)&A[(size_t)(j0 + r) * 1024 + kk + f4 * 4];
                Bs[f4 * 4 + 0][r] = vb.x;
                Bs[f4 * 4 + 1][r] = vb.y;
                Bs[f4 * 4 + 2][r] = vb.z;
                Bs[f4 * 4 + 3][r] = vb.w;
            }
            __syncthreads();
            #pragma unroll
            for (int k = 0; k < 64; k++) {
                float4 a = *(const float4*)&As[k][ty * 4];
                ulonglong2 bv = *(const ulonglong2*)&Bs[k][tx * 4];
                unsigned long long p0, p1, p2, p3;
                asm("mov.b64 %0,{%1,%1};" : "=l"(p0) : "f"(a.x));
                asm("mov.b64 %0,{%1,%1};" : "=l"(p1) : "f"(a.y));
                asm("mov.b64 %0,{%1,%1};" : "=l"(p2) : "f"(a.z));
                asm("mov.b64 %0,{%1,%1};" : "=l"(p3) : "f"(a.w));
                asm("fma.rn.f32x2 %0,%1,%2,%0;" : "+l"(acc[0][0]) : "l"(p0), "l"(bv.x));
                asm("fma.rn.f32x2 %0,%1,%2,%0;" : "+l"(acc[0][1]) : "l"(p0), "l"(bv.y));
                asm("fma.rn.f32x2 %0,%1,%2,%0;" : "+l"(acc[1][0]) : "l"(p1), "l"(bv.x));
                asm("fma.rn.f32x2 %0,%1,%2,%0;" : "+l"(acc[1][1]) : "l"(p1), "l"(bv.y));
                asm("fma.rn.f32x2 %0,%1,%2,%0;" : "+l"(acc[2][0]) : "l"(p2), "l"(bv.x));
                asm("fma.rn.f32x2 %0,%1,%2,%0;" : "+l"(acc[2][1]) : "l"(p2), "l"(bv.y));
                asm("fma.rn.f32x2 %0,%1,%2,%0;" : "+l"(acc[3][0]) : "l"(p3), "l"(bv.x));
                asm("fma.rn.f32x2 %0,%1,%2,%0;" : "+l"(acc[3][1]) : "l"(p3), "l"(bv.y));
            }
            __syncthreads();
        }
        const float scale = 1.0f / 4096.0f;   // (1/64)^2
        #pragma unroll
        for (int uu = 0; uu < 4; uu++) {
            #pragma unroll
            for (int vp = 0; vp < 2; vp++) {
                float lo, hi;
                asm("mov.b64 {%0,%1},%2;" : "=f"(lo), "=f"(hi) : "l"(acc[uu][vp]));
                int r  = i0 + ty * 4 + uu;
                int c0 = j0 + tx * 4 + 2 * vp;
                float vlo = lo * scale, vhi = hi * scale;
                g_gram[ks][t][r][c0 + 0] = vlo;
                g_gram[ks][t][r][c0 + 1] = vhi;
                g_gram[ks][t][c0 + 0][r] = vlo;  // mirror: bit-identical (commutative)
                g_gram[ks][t][c0 + 1][r] = vhi;
            }
        }
    }

    grid_barrier(&g_bar2);

    // ================= phase 3: ListMLE per row + final mean =================
    if (blockIdx.x < 256) {
        int i = blockIdx.x;
        float* tr = (float*)s_raw;            // 256 floats
        float* ps = (float*)(s_raw + 1024);   // 256 floats

        float p = 0.f, t = 0.f;
        #pragma unroll
        for (int ks = 0; ks < CK; ks++) {
            p += g_gram[ks][0][i][tid];   // pred
            t += g_gram[ks][1][i][tid];   // true
        }
        tr[tid] = t;
        __syncthreads();

        // stable descending rank (ties keep ascending index = argsort(-true))
        int rank = 0;
        #pragma unroll 8
        for (int k = 0; k < 256; k++) {
            float tk = tr[k];
            rank += (tk > t) || (tk == t && k < tid);
        }
        ps[rank] = p;
        __syncthreads();

        float psv = ps[tid];
        float s = __expf(psv);

        // warp inclusive suffix scan
        #pragma unroll
        for (int off = 1; off < 32; off <<= 1) {
            float v = __shfl_down_sync(0xffffffffu, s, off);
            if (lane + off < 32) s += v;
        }
        if (lane == 0) s_red[w] = s;
        __syncthreads();
        float tail = 0.f;
        #pragma unroll
        for (int w2 = 0; w2 < 8; w2++) if (w2 > w) tail += s_red[w2];
        float cs = s + tail;

        float term = __logf(cs + 1e-10f) - psv;
        __syncthreads();
        #pragma unroll
        for (int o = 16; o; o >>= 1) term += __shfl_xor_sync(0xffffffffu, term, o);
        if (lane == 0) s_red[w] = term;
        __syncthreads();
        if (tid == 0) {
            float sm = 0.f;
            #pragma unroll
            for (int w2 = 0; w2 < 8; w2++) sm += s_red[w2];
            g_rowloss[i] = sm;
            __threadfence();
            int v = atomicAdd(&g_done, 1);
            s_last = (v == 255);
        }
        __syncthreads();

        if (s_last) {
            volatile float* rl = g_rowloss;
            float v = rl[tid];
            #pragma unroll
            for (int o = 16; o; o >>= 1) v += __shfl_xor_sync(0xffffffffu, v, o);
            if (lane == 0) s_red[w] = v;
            __syncthreads();
            if (tid == 0) {
                float sm = 0.f;
                #pragma unroll
                for (int w2 = 0; w2 < 8; w2++) sm += s_red[w2];
                out[0] = sm * (1.0f / 256.0f);
                g_done = 0;   // reset counters for next graph replay
                g_bar1 = 0;
                g_bar2 = 0;
            }
        }
    }
}

// ---------------- launch ----------------
extern "C" void kernel_launch(void* const* d_in, const int* in_sizes, int n_in,
                              void* d_out, int out_size) {
    const float* emb  = (const float*)d_in[0];
    const float* feat = (const float*)d_in[1];
    float* out = (float*)d_out;

    cudaFuncSetAttribute(fused_kernel,
                         cudaFuncAttributeMaxDynamicSharedMemorySize, SMEM_BYTES);
    fused_kernel<<<GRID, 256, SMEM_BYTES>>>(emb, feat, out);
}

// round 8
// speedup vs baseline: 1.1065x; 1.1065x over previous
#include <cuda_runtime.h>
#include <math.h>

#define GRID 512          // 4 blocks/SM (128 thr) -> all 512 co-resident on 148 SMs
#define CK 16             // k-split for gram: 2*16*CK = 512 blocks exactly
#define SMEM_BYTES 49152  // 48 KB dynamic: 3 stages x 4 warps x 4 KB

// ---------------- scratch (device globals; no allocations) ----------------
__device__ float g_means[2][256][1024];    // per-tensor class sum-of-normalized vectors
__device__ float g_gram[CK][2][256][256];  // partial grams (8 MB, L2-resident)
__device__ float g_rowloss[256];
__device__ int   g_bar1, g_bar2, g_done;   // barrier counters (self-resetting)

__device__ __forceinline__ void grid_barrier(int* ctr) {
    __syncthreads();
    if (threadIdx.x == 0) {
        __threadfence();
        atomicAdd(ctr, 1);
        while (*((volatile int*)ctr) < GRID) __nanosleep(64);
    }
    __syncthreads();
}

extern __shared__ __align__(16) unsigned char s_raw[];

__global__ void __launch_bounds__(128, 4)
fused_kernel(const float* __restrict__ emb, const float* __restrict__ feat,
             float* __restrict__ out) {
    __shared__ float s_red[4];
    __shared__ int   s_last;

    int tid = threadIdx.x, lane = tid & 31, w = tid >> 5;

    // ================= phase 1: fused normalize + class mean =================
    // EXACTLY one (tensor,class) unit per block: 4 warps x 16 samples.
    // 3-stage warp-private cp.async staging; wait_group 2 -> 8 KB/warp in flight.
    {
        float4* sm4 = (float4*)s_raw;   // [(stage*4 + warp)*256 + pos]

        int u = blockIdx.x;             // 0..511
        int c = u & 255, t = u >> 8;
        const float4* base4 = (const float4*)((t == 0 ? emb : feat)
                               + (size_t)c * 65536) + (size_t)(w * 16) * 256;

        float4 acc[8];
        #pragma unroll
        for (int j = 0; j < 8; j++) acc[j] = make_float4(0.f, 0.f, 0.f, 0.f);

        #define ISSUE(n, st) do {                                                 \
            unsigned _d = (unsigned)__cvta_generic_to_shared(                     \
                              &sm4[((st) * 4 + w) * 256 + lane]);                 \
            const float4* _s = base4 + (size_t)(n) * 256 + lane;                  \
            _Pragma("unroll")                                                     \
            for (int j = 0; j < 8; j++)                                           \
                asm volatile("cp.async.cg.shared.global [%0], [%1], 16;"          \
                             :: "r"(_d + j * 512), "l"(_s + j * 32));             \
            asm volatile("cp.async.commit_group;");                               \
        } while (0)

        ISSUE(0, 0); ISSUE(1, 1); ISSUE(2, 2);

        #pragma unroll 1
        for (int n = 0; n < 16; n++) {
            asm volatile("cp.async.wait_group 2;" ::: "memory");
            int st = n % 3;
            const float4* sb = &sm4[(st * 4 + w) * 256];

            float4 v[8];
            #pragma unroll
            for (int j = 0; j < 8; j++) v[j] = sb[j * 32 + lane];

            // free the stage immediately for the next prefetch
            if (n + 3 < 16) { ISSUE(n + 3, st); }
            else { asm volatile("cp.async.commit_group;"); }

            float ss = 0.f;
            #pragma unroll
            for (int j = 0; j < 8; j++)
                ss += v[j].x * v[j].x + v[j].y * v[j].y
                    + v[j].z * v[j].z + v[j].w * v[j].w;
            #pragma unroll
            for (int o = 16; o; o >>= 1) ss += __shfl_xor_sync(0xffffffffu, ss, o);
            float inv = 1.0f / fmaxf(sqrtf(ss), 1e-12f);

            #pragma unroll
            for (int j = 0; j < 8; j++) {
                acc[j].x += v[j].x * inv;
                acc[j].y += v[j].y * inv;
                acc[j].z += v[j].z * inv;
                acc[j].w += v[j].w * inv;
            }
        }
        #undef ISSUE

        // cross-warp combine in staging area (each warp drained its own groups)
        __syncthreads();
        #pragma unroll
        for (int j = 0; j < 8; j++) sm4[w * 256 + j * 32 + lane] = acc[j];
        __syncthreads();
        #pragma unroll
        for (int i2 = tid; i2 < 256; i2 += 128) {
            float4 r = sm4[i2];
            #pragma unroll
            for (int w2 = 1; w2 < 4; w2++) {
                float4 vv = sm4[w2 * 256 + i2];
                r.x += vv.x; r.y += vv.y; r.z += vv.z; r.w += vv.w;
            }
            ((float4*)&g_means[t][c][0])[i2] = r;  // SUM; /64 folded into gram scale
        }
    }

    grid_barrier(&g_bar1);

    // ================= phase 2: gram = means @ means^T =================
    // 512 blocks exactly: tensor(2) x tile(16: 4x4 of 64x64) x ks(CK=16, k=64).
    // 128 threads, 8x4 micro-tile, fma.rn.f32x2 inner loop. No mirror: balance wins.
    {
        int b    = blockIdx.x;
        int ks   = b & 15;
        int it   = b >> 4;          // 0..31
        int t    = it >> 4;
        int tile = it & 15;
        int i0 = (tile >> 2) * 64, j0 = (tile & 3) * 64;
        const float* A = &g_means[t][0][0];

        float (*As)[68] = (float(*)[68])s_raw;             // 64x68 (17408 B)
        float (*Bs)[68] = (float(*)[68])(s_raw + 17408);

        int tx = tid & 15, ty = tid >> 4;   // 16 x 8
        unsigned long long acc[8][2];       // 8 rows x 4 cols (2 packed pairs)
        #pragma unroll
        for (int uu = 0; uu < 8; uu++) { acc[uu][0] = 0ull; acc[uu][1] = 0ull; }

        int kk = ks * 64;
        #pragma unroll
        for (int l = 0; l < 8; l++) {
            int idx = tid + l * 128;
            int r = idx >> 4, f4 = idx & 15;
            float4 va = *(const float4*)&A[(size_t)(i0 + r) * 1024 + kk + f4 * 4];
            As[f4 * 4 + 0][r] = va.x;
            As[f4 * 4 + 1][r] = va.y;
            As[f4 * 4 + 2][r] = va.z;
            As[f4 * 4 + 3][r] = va.w;
            float4 vb = *(const float4*)&A[(size_t)(j0 + r) * 1024 + kk + f4 * 4];
            Bs[f4 * 4 + 0][r] = vb.x;
            Bs[f4 * 4 + 1][r] = vb.y;
            Bs[f4 * 4 + 2][r] = vb.z;
            Bs[f4 * 4 + 3][r] = vb.w;
        }
        __syncthreads();
        #pragma unroll 4
        for (int k = 0; k < 64; k++) {
            float4 a0 = *(const float4*)&As[k][ty * 8];
            float4 a1 = *(const float4*)&As[k][ty * 8 + 4];
            ulonglong2 bv = *(const ulonglong2*)&Bs[k][tx * 4];
            unsigned long long p0, p1, p2, p3, p4, p5, p6, p7;
            asm("mov.b64 %0,{%1,%1};" : "=l"(p0) : "f"(a0.x));
            asm("mov.b64 %0,{%1,%1};" : "=l"(p1) : "f"(a0.y));
            asm("mov.b64 %0,{%1,%1};" : "=l"(p2) : "f"(a0.z));
            asm("mov.b64 %0,{%1,%1};" : "=l"(p3) : "f"(a0.w));
            asm("mov.b64 %0,{%1,%1};" : "=l"(p4) : "f"(a1.x));
            asm("mov.b64 %0,{%1,%1};" : "=l"(p5) : "f"(a1.y));
            asm("mov.b64 %0,{%1,%1};" : "=l"(p6) : "f"(a1.z));
            asm("mov.b64 %0,{%1,%1};" : "=l"(p7) : "f"(a1.w));
            asm("fma.rn.f32x2 %0,%1,%2,%0;" : "+l"(acc[0][0]) : "l"(p0), "l"(bv.x));
            asm("fma.rn.f32x2 %0,%1,%2,%0;" : "+l"(acc[0][1]) : "l"(p0), "l"(bv.y));
            asm("fma.rn.f32x2 %0,%1,%2,%0;" : "+l"(acc[1][0]) : "l"(p1), "l"(bv.x));
            asm("fma.rn.f32x2 %0,%1,%2,%0;" : "+l"(acc[1][1]) : "l"(p1), "l"(bv.y));
            asm("fma.rn.f32x2 %0,%1,%2,%0;" : "+l"(acc[2][0]) : "l"(p2), "l"(bv.x));
            asm("fma.rn.f32x2 %0,%1,%2,%0;" : "+l"(acc[2][1]) : "l"(p2), "l"(bv.y));
            asm("fma.rn.f32x2 %0,%1,%2,%0;" : "+l"(acc[3][0]) : "l"(p3), "l"(bv.x));
            asm("fma.rn.f32x2 %0,%1,%2,%0;" : "+l"(acc[3][1]) : "l"(p3), "l"(bv.y));
            asm("fma.rn.f32x2 %0,%1,%2,%0;" : "+l"(acc[4][0]) : "l"(p4), "l"(bv.x));
            asm("fma.rn.f32x2 %0,%1,%2,%0;" : "+l"(acc[4][1]) : "l"(p4), "l"(bv.y));
            asm("fma.rn.f32x2 %0,%1,%2,%0;" : "+l"(acc[5][0]) : "l"(p5), "l"(bv.x));
            asm("fma.rn.f32x2 %0,%1,%2,%0;" : "+l"(acc[5][1]) : "l"(p5), "l"(bv.y));
            asm("fma.rn.f32x2 %0,%1,%2,%0;" : "+l"(acc[6][0]) : "l"(p6), "l"(bv.x));
            asm("fma.rn.f32x2 %0,%1,%2,%0;" : "+l"(acc[6][1]) : "l"(p6), "l"(bv.y));
            asm("fma.rn.f32x2 %0,%1,%2,%0;" : "+l"(acc[7][0]) : "l"(p7), "l"(bv.x));
            asm("fma.rn.f32x2 %0,%1,%2,%0;" : "+l"(acc[7][1]) : "l"(p7), "l"(bv.y));
        }
        const float scale = 1.0f / 4096.0f;   // (1/64)^2
        #pragma unroll
        for (int uu = 0; uu < 8; uu++) {
            #pragma unroll
            for (int vp = 0; vp < 2; vp++) {
                float lo, hi;
                asm("mov.b64 {%0,%1},%2;" : "=f"(lo), "=f"(hi) : "l"(acc[uu][vp]));
                int r  = i0 + ty * 8 + uu;
                int c0 = j0 + tx * 4 + 2 * vp;
                g_gram[ks][t][r][c0 + 0] = lo * scale;
                g_gram[ks][t][r][c0 + 1] = hi * scale;
            }
        }
    }

    grid_barrier(&g_bar2);

    // ================= phase 3: ListMLE per row + final mean =================
    if (blockIdx.x < 256) {
        int i = blockIdx.x;
        float* tr = (float*)s_raw;            // 256 floats
        float* ps = (float*)(s_raw + 1024);   // 256 floats

        float p0 = 0.f, t0 = 0.f, p1 = 0.f, t1 = 0.f;
        #pragma unroll
        for (int ks = 0; ks < CK; ks++) {
            p0 += g_gram[ks][0][i][tid];
            p1 += g_gram[ks][0][i][tid + 128];
            t0 += g_gram[ks][1][i][tid];
            t1 += g_gram[ks][1][i][tid + 128];
        }
        tr[tid] = t0; tr[tid + 128] = t1;
        __syncthreads();

        // stable descending rank (ties keep ascending index = argsort(-true))
        int r0 = 0, r1 = 0;
        #pragma unroll 8
        for (int k = 0; k < 256; k++) {
            float tk = tr[k];
            r0 += (tk > t0) || (tk == t0 && k < tid);
            r1 += (tk > t1) || (tk == t1 && k < tid + 128);
        }
        ps[r0] = p0;
        ps[r1] = p1;
        __syncthreads();

        // thread owns sorted positions (2*tid, 2*tid+1)
        float e0 = ps[2 * tid], e1 = ps[2 * tid + 1];
        float x0 = __expf(e0), x1 = __expf(e1);
        float s = x0 + x1;

        #pragma unroll
        for (int off = 1; off < 32; off <<= 1) {
            float v = __shfl_down_sync(0xffffffffu, s, off);
            if (lane + off < 32) s += v;
        }
        if (lane == 0) s_red[w] = s;
        __syncthreads();
        float tail = 0.f;
        #pragma unroll
        for (int w2 = 0; w2 < 4; w2++) if (w2 > w) tail += s_red[w2];
        float S = s + tail;                 // suffix sum at position 2*tid

        float term = (__logf(S + 1e-10f) - e0)
                   + (__logf(S - x0 + 1e-10f) - e1);
        __syncthreads();
        #pragma unroll
        for (int o = 16; o; o >>= 1) term += __shfl_xor_sync(0xffffffffu, term, o);
        if (lane == 0) s_red[w] = term;
        __syncthreads();
        if (tid == 0) {
            g_rowloss[i] = s_red[0] + s_red[1] + s_red[2] + s_red[3];
            __threadfence();
            int v = atomicAdd(&g_done, 1);
            s_last = (v == 255);
        }
        __syncthreads();

        if (s_last) {
            volatile float* rl = g_rowloss;
            float v = rl[tid] + rl[tid + 128];
            #pragma unroll
            for (int o = 16; o; o >>= 1) v += __shfl_xor_sync(0xffffffffu, v, o);
            if (lane == 0) s_red[w] = v;
            __syncthreads();
            if (tid == 0) {
                out[0] = (s_red[0] + s_red[1] + s_red[2] + s_red[3]) * (1.0f / 256.0f);
                g_done = 0;   // reset counters for next graph replay
                g_bar1 = 0;
                g_bar2 = 0;
            }
        }
    }
}

// ---------------- launch ----------------
extern "C" void kernel_launch(void* const* d_in, const int* in_sizes, int n_in,
                              void* d_out, int out_size) {
    const float* emb  = (const float*)d_in[0];
    const float* feat = (const float*)d_in[1];
    float* out = (float*)d_out;

    cudaFuncSetAttribute(fused_kernel,
                         cudaFuncAttributeMaxDynamicSharedMemorySize, SMEM_BYTES);
    fused_kernel<<<GRID, 128, SMEM_BYTES>>>(emb, feat, out);
}